// round 11
// baseline (speedup 1.0000x reference)
#include <cuda_runtime.h>

typedef unsigned long long ull;
typedef unsigned int u32;

#define NB 32
#define LG 576
#define LL 256
#define NC 512
#define ND 8192
#define MG 20
#define ML 4

// ---------------- device scratch ----------------
__device__ ull   g_key_fg[NB * LG];
__device__ ull   g_key_gg[NB * LG];
__device__ ull   g_key_gl[NB * LL];
__device__ ull   g_colp[NB * 5 * LL];      // per-(batch,slot) col-argmin partials
__device__ float g_statp[32][8];           // per-block VICReg stat partials
__device__ __align__(16) float g_Rp[2][32][1024];
__device__ float g_acc[16];                // 5..8: mse sums
__device__ int   g_done;

__device__ __forceinline__ ull packkey(float d, int i) {
    return (((ull)__float_as_uint(d)) << 32) | (unsigned)i;
}

#define MMA_BF16(C, A, B0, B1)                                              \
    asm volatile("mma.sync.aligned.m16n8k16.row.col.f32.bf16.bf16.f32 "     \
                 "{%0,%1,%2,%3}, {%4,%5,%6,%7}, {%8,%9}, {%0,%1,%2,%3};"    \
                 : "+f"((C)[0]), "+f"((C)[1]), "+f"((C)[2]), "+f"((C)[3])   \
                 : "r"((A)[0]), "r"((A)[1]), "r"((A)[2]), "r"((A)[3]),      \
                   "r"(B0), "r"(B1))

__device__ __forceinline__ u32 packbf(float lo, float hi) {
    u32 r; asm("cvt.rn.bf16x2.f32 %0, %1, %2;" : "=r"(r) : "f"(hi), "f"(lo)); return r;
}

__device__ float block_reduce(float v, float* sh) {
    __syncthreads();
    int lane = threadIdx.x & 31, wid = threadIdx.x >> 5;
#pragma unroll
    for (int o = 16; o; o >>= 1) v += __shfl_down_sync(0xffffffffu, v, o);
    if (lane == 0) sh[wid] = v;
    __syncthreads();
    float r = 0.f;
    if (wid == 0) {
        int nw = (blockDim.x + 31) >> 5;
        r = (lane < nw) ? sh[lane] : 0.f;
#pragma unroll
        for (int o = 16; o; o >>= 1) r += __shfl_down_sync(0xffffffffu, r, o);
    }
    return r;  // valid on thread 0
}

// ================= mega kernel =================
// blocks 0..159: cdist, 2 m-tiles per block (bb=blk/5, slot=blk%5, tiles 2s,2s+1)
// 160..191: VICReg stats; 192..255: split-K gram; 256..319: grid NN; 320: init.
struct __align__(16) CdistSm {
    u32 As[1024];        // [ks][mfrag][reg][lane^swz]
    u32 Bs[4096];
    ull rowKey[64];
    ull colKey[LL];
    float rowN[64];
    float colN[LL];
};
union __align__(16) MegaSm {
    CdistSm c;
    float gram[32][257];
    float2 sc[LG];
    float sh[18];
};

__global__ void __launch_bounds__(256, 2) mega_kernel(const float* __restrict__ za,
                                                      const float* __restrict__ zb,
                                                      const float* __restrict__ fg,
                                                      const float* __restrict__ fl,
                                                      const float* __restrict__ gg_in,
                                                      const float* __restrict__ gl_in) {
    __shared__ MegaSm sm;
    int blk = blockIdx.x, tid = threadIdx.x;

    if (blk < 160) {
        // ---------------- cdist branch: up to 2 m-tiles ----------------
        int bb = blk / 5, slot = blk % 5;
        const float* A = fg + (size_t)bb * LG * NC;
        const float* B = fl + (size_t)bb * LL * NC;
        int lane = tid & 31, warp = tid >> 5;
        int mw = warp >> 2, nw = warp & 3;

        sm.c.colKey[tid] = ~0ULL;

        // loader roles (tile-independent parts)
        int ar = tid >> 2, aq = tid & 3;
        int p0a = aq * 4;
        int aks = p0a >> 3, ahalf = (p0a & 7) >> 2;
        int areg = ahalf * 2 + ((ar & 15) >> 3);
        int alb = ((ar & 7) * 4) ^ (aks << 2) ^ (ahalf << 4);
        int aoff = (((aks * 4 + (ar >> 4)) * 4 + areg) * 32) + alb;

        int boff[4]; const float4* bptr[4]; int brow[4];
#pragma unroll
        for (int i = 0; i < 4; i++) {
            int f = tid + i * 256;
            int n = f >> 2, p0 = (f & 3) * 4;
            int ks = p0 >> 3, reg = (p0 & 7) >> 2;
            int lb = ((n & 7) * 4) ^ (ks << 2) ^ (reg << 4);
            boff[i] = (((ks * 32 + (n >> 3)) * 2 + reg) * 32) + lb;
            bptr[i] = (const float4*)(B + (size_t)n * NC) + (f & 3) * 2;
            brow[i] = n;
        }

        for (int sub = 0; sub < 2; sub++) {
            int mt = slot * 2 + sub;
            if (mt >= 9) break;
            int mo = mt * 64;
            const float4* aptr = (const float4*)(A + (size_t)(mo + ar) * NC) + aq * 2;

            if (tid < 64) sm.c.rowKey[tid] = ~0ULL;

            float nA = 0.f, nBr[4] = {0.f, 0.f, 0.f, 0.f};
            u32 au[4], bu[4][4];

#define LDGCONV(CH)                                                          \
            do {                                                             \
                float4 v0 = aptr[(CH) * 8], v1 = aptr[(CH) * 8 + 1];         \
                nA += v0.x*v0.x + v0.y*v0.y + v0.z*v0.z + v0.w*v0.w          \
                    + v1.x*v1.x + v1.y*v1.y + v1.z*v1.z + v1.w*v1.w;         \
                au[0] = packbf(v0.x, v0.y); au[1] = packbf(v0.z, v0.w);      \
                au[2] = packbf(v1.x, v1.y); au[3] = packbf(v1.z, v1.w);      \
                _Pragma("unroll")                                            \
                for (int i_ = 0; i_ < 4; i_++) {                             \
                    float4 w0 = bptr[i_][(CH) * 8], w1 = bptr[i_][(CH) * 8 + 1]; \
                    nBr[i_] += w0.x*w0.x + w0.y*w0.y + w0.z*w0.z + w0.w*w0.w \
                             + w1.x*w1.x + w1.y*w1.y + w1.z*w1.z + w1.w*w1.w;\
                    bu[i_][0] = packbf(w0.x, w0.y); bu[i_][1] = packbf(w0.z, w0.w); \
                    bu[i_][2] = packbf(w1.x, w1.y); bu[i_][3] = packbf(w1.z, w1.w); \
                }                                                            \
            } while (0)

            float acc[2][8][4];
#pragma unroll
            for (int i = 0; i < 2; i++)
#pragma unroll
                for (int j = 0; j < 8; j++)
#pragma unroll
                    for (int k = 0; k < 4; k++) acc[i][j][k] = 0.f;

            LDGCONV(0);
            for (int ch = 0; ch < 16; ch++) {
                *(uint4*)&sm.c.As[aoff] = make_uint4(au[0], au[1], au[2], au[3]);
#pragma unroll
                for (int i = 0; i < 4; i++)
                    *(uint4*)&sm.c.Bs[boff[i]] = make_uint4(bu[i][0], bu[i][1], bu[i][2], bu[i][3]);
                __syncthreads();
                if (ch < 15) LDGCONV(ch + 1);
#pragma unroll
                for (int ks = 0; ks < 2; ks++) {
                    u32 a[2][4];
#pragma unroll
                    for (int m2 = 0; m2 < 2; m2++) {
                        int mf = mw * 2 + m2;
                        int base = ((ks * 4 + mf) * 4) * 32;
#pragma unroll
                        for (int rg = 0; rg < 4; rg++)
                            a[m2][rg] = sm.c.As[base + rg * 32 + (lane ^ (ks << 2) ^ ((rg >> 1) << 4))];
                    }
#pragma unroll
                    for (int n2 = 0; n2 < 8; n2++) {
                        int nf = nw * 8 + n2;
                        u32 b0 = sm.c.Bs[((ks * 32 + nf) * 2 + 0) * 32 + (lane ^ (ks << 2))];
                        u32 b1 = sm.c.Bs[((ks * 32 + nf) * 2 + 1) * 32 + (lane ^ (ks << 2) ^ 16)];
                        MMA_BF16(acc[0][n2], a[0], b0, b1);
                        MMA_BF16(acc[1][n2], a[1], b0, b1);
                    }
                }
                __syncthreads();
            }

            // finish norms (4-lane aligned groups)
            nA += __shfl_xor_sync(0xffffffffu, nA, 1);
            nA += __shfl_xor_sync(0xffffffffu, nA, 2);
            if (aq == 0) sm.c.rowN[ar] = nA;
#pragma unroll
            for (int i = 0; i < 4; i++) {
                float v = nBr[i];
                v += __shfl_xor_sync(0xffffffffu, v, 1);
                v += __shfl_xor_sync(0xffffffffu, v, 2);
                if ((tid & 3) == 0) sm.c.colN[brow[i]] = v;
            }
            __syncthreads();

            float naR[2][2], nbC[8][2];
#pragma unroll
            for (int m2 = 0; m2 < 2; m2++)
#pragma unroll
                for (int rh = 0; rh < 2; rh++)
                    naR[m2][rh] = sm.c.rowN[(mw * 2 + m2) * 16 + (lane >> 2) + rh * 8];
#pragma unroll
            for (int n2 = 0; n2 < 8; n2++)
#pragma unroll
                for (int h = 0; h < 2; h++)
                    nbC[n2][h] = sm.c.colN[nw * 64 + n2 * 8 + (lane & 3) * 2 + h];

#pragma unroll
            for (int m2 = 0; m2 < 2; m2++)
#pragma unroll
                for (int rh = 0; rh < 2; rh++) {
                    ull best = ~0ULL;
#pragma unroll
                    for (int n2 = 0; n2 < 8; n2++)
#pragma unroll
                        for (int h = 0; h < 2; h++) {
                            float d = fmaxf(naR[m2][rh] + nbC[n2][h] - 2.f * acc[m2][n2][rh * 2 + h], 0.f);
                            ull k = packkey(d, nw * 64 + n2 * 8 + (lane & 3) * 2 + h);
                            best = (k < best) ? k : best;
                        }
                    ull o = __shfl_xor_sync(0xffffffffu, best, 1); best = (o < best) ? o : best;
                    o = __shfl_xor_sync(0xffffffffu, best, 2);     best = (o < best) ? o : best;
                    if ((lane & 3) == 0)
                        atomicMin(&sm.c.rowKey[(mw * 2 + m2) * 16 + (lane >> 2) + rh * 8], best);
                }

#pragma unroll
            for (int n2 = 0; n2 < 8; n2++)
#pragma unroll
                for (int h = 0; h < 2; h++) {
                    ull best = ~0ULL;
#pragma unroll
                    for (int m2 = 0; m2 < 2; m2++)
#pragma unroll
                        for (int rh = 0; rh < 2; rh++) {
                            float d = fmaxf(naR[m2][rh] + nbC[n2][h] - 2.f * acc[m2][n2][rh * 2 + h], 0.f);
                            ull k = packkey(d, mo + (mw * 2 + m2) * 16 + (lane >> 2) + rh * 8);
                            best = (k < best) ? k : best;
                        }
                    ull o = __shfl_xor_sync(0xffffffffu, best, 4);  best = (o < best) ? o : best;
                    o = __shfl_xor_sync(0xffffffffu, best, 8);      best = (o < best) ? o : best;
                    o = __shfl_xor_sync(0xffffffffu, best, 16);     best = (o < best) ? o : best;
                    if (lane < 4)
                        atomicMin(&sm.c.colKey[nw * 64 + n2 * 8 + (lane & 3) * 2 + h], best);
                }
            __syncthreads();
            if (tid < 64) g_key_fg[(size_t)bb * LG + mo + tid] = sm.c.rowKey[tid];
            __syncthreads();
        }
        g_colp[((size_t)bb * 5 + slot) * LL + tid] = sm.c.colKey[tid];
    } else if (blk < 192) {
        // ---------------- VICReg per-dim stats (partials) ----------------
        int idx = blk - 160;
        int j = idx * 256 + tid;
        float sa = 0, sqa = 0, sb = 0, sqb = 0, sd = 0;
#pragma unroll 8
        for (int i = 0; i < 32; i++) {
            float x = za[(size_t)i * ND + j], y = zb[(size_t)i * ND + j];
            sa += x; sqa += x * x; sb += y; sqb += y * y;
            float df = x - y; sd += df * df;
        }
        float s_a = sqa - sa * sa * (1.f / 32.f);
        float s_b = sqb - sb * sb * (1.f / 32.f);
        float va = fmaxf(0.f, 1.f - sqrtf(s_a * (1.f / 31.f) + 1e-4f));
        float vb = fmaxf(0.f, 1.f - sqrtf(s_b * (1.f / 31.f) + 1e-4f));
        float r;
        r = block_reduce(va, sm.sh);         if (tid == 0) g_statp[idx][0] = r;
        r = block_reduce(vb, sm.sh);         if (tid == 0) g_statp[idx][1] = r;
        r = block_reduce(s_a * s_a, sm.sh);  if (tid == 0) g_statp[idx][2] = r;
        r = block_reduce(s_b * s_b, sm.sh);  if (tid == 0) g_statp[idx][3] = r;
        r = block_reduce(sd, sm.sh);         if (tid == 0) g_statp[idx][4] = r;
    } else if (blk < 256) {
        // ---------------- split-K gram ----------------
        int idx = blk - 192;
        int mat = idx >> 5, chunk = idx & 31;
        int d0 = chunk * 256;
        const float* z = mat ? zb : za;
        for (int i = tid; i < 2048; i += 256) {
            int row = i >> 6, c4 = i & 63;
            float4 v = *(const float4*)(z + (size_t)row * ND + d0 + c4 * 4);
            sm.gram[row][c4 * 4 + 0] = v.x; sm.gram[row][c4 * 4 + 1] = v.y;
            sm.gram[row][c4 * 4 + 2] = v.z; sm.gram[row][c4 * 4 + 3] = v.w;
        }
        __syncthreads();
        int ia = tid >> 3, kb = (tid & 7) * 4;
        float c[4] = {};
        for (int d = 0; d < 256; d++) {
            float av = sm.gram[ia][d];
#pragma unroll
            for (int j = 0; j < 4; j++) c[j] = fmaf(av, sm.gram[kb + j][d], c[j]);
        }
#pragma unroll
        for (int j = 0; j < 4; j++) g_Rp[mat][chunk][ia * 32 + kb + j] = c[j];
    } else if (blk < 320) {
        // ---------------- grid-space NN ----------------
        int idx = blk - 256;
        int bb = idx >> 1, dir = idx & 1;
        int Lin = dir ? LL : LG, Lc = dir ? LG : LL;
        const float* gin   = dir ? gl_in : gg_in;
        const float* gcand = dir ? gg_in : gl_in;
        ull* keyout = dir ? g_key_gl : g_key_gg;
        const float2* gc = (const float2*)gcand + (size_t)bb * Lc;
        for (int i = tid; i < Lc; i += 256) sm.sc[i] = gc[i];
        __syncthreads();
        const float2* gi = (const float2*)gin + (size_t)bb * Lin;
        for (int l = tid; l < Lin; l += 256) {
            float2 g = gi[l];
            float best = 3.4e38f; int bi = 0;
            for (int m = 0; m < Lc; m++) {
                float dx = g.x - sm.sc[m].x, dy = g.y - sm.sc[m].y;
                float d = dx * dx + dy * dy;
                if (d < best) { best = d; bi = m; }
            }
            keyout[(size_t)bb * Lin + l] = packkey(best, bi);
        }
    } else {
        if (tid < 16) g_acc[tid] = 0.f;
        if (tid == 16) g_done = 0;
    }
}

// ================= selection + MSE + last-block finale =================
// grid (NB, 4), 576 threads; single wave. Rank by (dist, row) via unique u64 key.
__global__ void __launch_bounds__(576) selmse_final(const float* __restrict__ fG,
                                                    const float* __restrict__ fL,
                                                    float* __restrict__ out, int out_size) {
    int bb = blockIdx.x, which = blockIdx.y;
    int tid = threadIdx.x, lane = tid & 31, wid = tid >> 5;

    __shared__ ull sk[LG];
    __shared__ ull sk2[LG];
    __shared__ int selsh[MG];
    __shared__ int candsh[MG];
    __shared__ int warpcnt[18];
    __shared__ float shred[18];

    {
        const float* fin; const float* fc;
        int Lin, Lc, Msel;
        if (which == 0)      { fin = fG; fc = fL; Lin = LG; Lc = LL; Msel = MG; }
        else if (which == 1) { fin = fL; fc = fG; Lin = LL; Lc = LG; Msel = ML; }
        else if (which == 2) { fin = fG; fc = fL; Lin = LG; Lc = LL; Msel = MG; }
        else                 { fin = fL; fc = fG; Lin = LL; Lc = LG; Msel = ML; }
        int accIdx = 5 + which;

        if (tid < Lin) {
            ull k;
            if (which == 0)      k = g_key_fg[(size_t)bb * LG + tid];
            else if (which == 2) k = g_key_gg[(size_t)bb * LG + tid];
            else if (which == 3) k = g_key_gl[(size_t)bb * LL + tid];
            else {
                k = ~0ULL;
#pragma unroll
                for (int s = 0; s < 5; s++) {
                    ull o = g_colp[((size_t)bb * 5 + s) * LL + tid];
                    k = (o < k) ? o : k;
                }
            }
            sk[tid] = k;
            sk2[tid] = (k & 0xFFFFFFFF00000000ULL) | (unsigned)tid;  // (dist, row): unique
        }
        __syncthreads();

        int myflag = 0;
        if (tid < Lin) {
            ull mine = sk2[tid];
            int cnt = 0;
#pragma unroll 8
            for (int j = 0; j < Lin; j++) cnt += (sk2[j] < mine);
            myflag = (cnt < Msel) ? 1 : 0;
        }
        u32 bal = __ballot_sync(0xffffffffu, myflag);
        if (lane == 0) warpcnt[wid] = __popc(bal);
        __syncthreads();
        if (myflag) {
            int pos = __popc(bal & ((1u << lane) - 1u));
            for (int w = 0; w < wid; w++) pos += warpcnt[w];
            selsh[pos] = tid;
            candsh[pos] = (int)(sk[tid] & 0xffffffffULL);
        }
        __syncthreads();

        const float4* fin4 = (const float4*)(fin + (size_t)bb * Lin * NC);
        const float4* fc4  = (const float4*)(fc + (size_t)bb * Lc * NC);
        float s = 0.f;
        int total = Msel * (NC / 4);
        for (int idx = tid; idx < total; idx += 576) {
            int mi = idx >> 7, t = idx & 127;
            int row = selsh[mi], cand = candsh[mi];
            float4 x = fin4[row * 128 + t], y = fc4[cand * 128 + t];
            float dx = x.x - y.x, dy = x.y - y.y, dz = x.z - y.z, dw = x.w - y.w;
            s += dx * dx + dy * dy + dz * dz + dw * dw;
        }
#pragma unroll
        for (int o = 16; o; o >>= 1) s += __shfl_down_sync(0xffffffffu, s, o);
        if (lane == 0) shred[wid] = s;
        __syncthreads();
        if (wid == 0) {
            float r = (lane < 18) ? shred[lane] : 0.f;
#pragma unroll
            for (int o = 16; o; o >>= 1) r += __shfl_down_sync(0xffffffffu, r, o);
            if (lane == 0) atomicAdd(&g_acc[accIdx], r);
        }
    }

    // ---------------- last-block finale ----------------
    __shared__ int isLast;
    __threadfence();
    __syncthreads();
    if (tid == 0) isLast = (atomicAdd(&g_done, 1) == NB * 4 - 1) ? 1 : 0;
    __syncthreads();
    if (!isLast) return;

    __shared__ __align__(16) float sR[1024];
    __shared__ float rowsum[32];
    __shared__ float covG[2];
    __shared__ float statv[8];
    __shared__ float qsh;

    // stats partials: 5 stats x 32 blocks
    if (tid < 160) {
        int k = tid >> 5, l = tid & 31;
        float v = g_statp[l][k];
#pragma unroll
        for (int o = 16; o; o >>= 1) v += __shfl_down_sync(0xffffffffu, v, o);
        if (l == 0) statv[k] = v;
    }

    for (int mat = 0; mat < 2; mat++) {
        if (tid < 256) {
            float4 s4 = make_float4(0.f, 0.f, 0.f, 0.f);
#pragma unroll
            for (int c = 0; c < 32; c++) {
                float4 v = *((const float4*)&g_Rp[mat][c][0] + tid);
                s4.x += v.x; s4.y += v.y; s4.z += v.z; s4.w += v.w;
            }
            *(float4*)&sR[tid * 4] = s4;
        }
        __syncthreads();
        for (int r = wid; r < 32; r += 18) {
            float s = sR[r * 32 + lane];
#pragma unroll
            for (int o = 16; o; o >>= 1) s += __shfl_down_sync(0xffffffffu, s, o);
            if (lane == 0) rowsum[r] = s;
        }
        __syncthreads();
        if (wid == 0) {
            float s = rowsum[lane];
#pragma unroll
            for (int o = 16; o; o >>= 1) s += __shfl_down_sync(0xffffffffu, s, o);
            if (lane == 0) qsh = s * (1.f / 1024.f);
        }
        __syncthreads();
        float q = qsh;
        float part = 0.f;
        if (tid < 256) {
            float rsi = rowsum[tid >> 3] * (1.f / 32.f);
#pragma unroll
            for (int j = 0; j < 4; j++) {
                int t = tid * 4 + j;
                int k = t & 31;
                float g = sR[t] - rsi - rowsum[k] * (1.f / 32.f) + q;
                part += g * g;
            }
        }
        float tot = block_reduce(part, shred);
        if (tid == 0) covG[mat] = tot;
        __syncthreads();
    }
    if (tid == 0) {
        float inv_g = statv[4] * (1.f / (32.f * 8192.f));
        float v = 0.5f * (statv[0] + statv[1]) * (1.f / 8192.f);
        float cov = ((covG[0] - statv[2]) + (covG[1] - statv[3])) * (1.f / (31.f * 31.f * 8192.f));
        float global_loss = 25.f * inv_g + 25.f * v + 1.f * cov;
        float mfg = __ldcg(&g_acc[5]) * (1.f / (32.f * MG * NC));
        float mfl = __ldcg(&g_acc[6]) * (1.f / (32.f * ML * NC));
        float mgg = __ldcg(&g_acc[7]) * (1.f / (32.f * MG * NC));
        float mgl = __ldcg(&g_acc[8]) * (1.f / (32.f * ML * NC));
        float local_loss = 25.f * (0.5f * (mfg + mfl) + 0.5f * (mgg + mgl));
        float res = 0.25f * global_loss + 0.75f * local_loss;
        for (int i = 0; i < out_size; i++) out[i] = res;
    }
}

extern "C" void kernel_launch(void* const* d_in, const int* in_sizes, int n_in,
                              void* d_out, int out_size) {
    (void)in_sizes; (void)n_in;
    const float* zg = (const float*)d_in[0];   // (32, 8192)
    const float* zl = (const float*)d_in[1];   // (32, 8192)
    const float* fg = (const float*)d_in[2];   // (32, 576, 512)
    const float* fl = (const float*)d_in[3];   // (32, 256, 512)
    const float* gg = (const float*)d_in[4];   // (32, 576, 2)
    const float* gl = (const float*)d_in[5];   // (32, 256, 2)
    float* out = (float*)d_out;

    mega_kernel<<<321, 256>>>(zg, zl, fg, fl, gg, gl);
    {
        dim3 grid(NB, 4);
        selmse_final<<<grid, 576>>>(fg, fl, out, out_size);
    }
}

// round 12
// speedup vs baseline: 1.3868x; 1.3868x over previous
#include <cuda_runtime.h>

typedef unsigned long long ull;
typedef unsigned int u32;

#define NB 32
#define LG 576
#define LL 256
#define NC 512
#define ND 8192
#define MG 20
#define ML 4

// ---------------- device scratch ----------------
__device__ ull   g_key_fg[NB * LG];
__device__ ull   g_key_gg[NB * LG];
__device__ ull   g_key_gl[NB * LL];
__device__ ull   g_colp[NB * 9 * LL];      // per-(batch,mtile) col-argmin partials
__device__ float g_statp[32][8];           // per-block VICReg stat partials
__device__ __align__(16) float g_Rp[2][32][1024];
__device__ float g_acc[16];                // 5..8: mse sums

__device__ __forceinline__ ull packkey(float d, int i) {
    return (((ull)__float_as_uint(d)) << 32) | (unsigned)i;
}

#define MMA_BF16(C, A, B0, B1)                                              \
    asm volatile("mma.sync.aligned.m16n8k16.row.col.f32.bf16.bf16.f32 "     \
                 "{%0,%1,%2,%3}, {%4,%5,%6,%7}, {%8,%9}, {%0,%1,%2,%3};"    \
                 : "+f"((C)[0]), "+f"((C)[1]), "+f"((C)[2]), "+f"((C)[3])   \
                 : "r"((A)[0]), "r"((A)[1]), "r"((A)[2]), "r"((A)[3]),      \
                   "r"(B0), "r"(B1))

__device__ __forceinline__ u32 packbf(float lo, float hi) {
    u32 r; asm("cvt.rn.bf16x2.f32 %0, %1, %2;" : "=r"(r) : "f"(hi), "f"(lo)); return r;
}

__device__ float block_reduce(float v, float* sh) {
    __syncthreads();
    int lane = threadIdx.x & 31, wid = threadIdx.x >> 5;
#pragma unroll
    for (int o = 16; o; o >>= 1) v += __shfl_down_sync(0xffffffffu, v, o);
    if (lane == 0) sh[wid] = v;
    __syncthreads();
    float r = 0.f;
    if (wid == 0) {
        int nw = (blockDim.x + 31) >> 5;
        r = (lane < nw) ? sh[lane] : 0.f;
#pragma unroll
        for (int o = 16; o; o >>= 1) r += __shfl_down_sync(0xffffffffu, r, o);
    }
    return r;  // valid on thread 0
}

// ================= mega kernel (R9 structure: 1 m-tile per cdist block) =================
// blocks 0..287: cdist (bb=blk/9, mtile=blk%9); 288..319: VICReg stats;
// 320..383: split-K gram; 384..447: grid NN; 448: init.
struct __align__(16) CdistSm {
    u32 As[1024];        // [ks][mfrag][reg][lane^swz]
    u32 Bs[4096];
    ull rowKey[64];
    ull colKey[LL];
    float rowN[64];
    float colN[LL];
};
union __align__(16) MegaSm {
    CdistSm c;
    float gram[32][257];
    float2 sc[LG];
    float sh[18];
};

__global__ void __launch_bounds__(256, 2) mega_kernel(const float* __restrict__ za,
                                                      const float* __restrict__ zb,
                                                      const float* __restrict__ fg,
                                                      const float* __restrict__ fl,
                                                      const float* __restrict__ gg_in,
                                                      const float* __restrict__ gl_in) {
    __shared__ MegaSm sm;
    int blk = blockIdx.x, tid = threadIdx.x;

    if (blk < 288) {
        // ---------------- cdist branch ----------------
        int bb = blk / 9, mt = blk % 9, mo = mt * 64;
        const float* A = fg + (size_t)bb * LG * NC;
        const float* B = fl + (size_t)bb * LL * NC;
        int lane = tid & 31, warp = tid >> 5;
        int mw = warp >> 2, nw = warp & 3;

        if (tid < 64) sm.c.rowKey[tid] = ~0ULL;
        sm.c.colKey[tid] = ~0ULL;

        // A loader role: 4 threads per row, 8 f32 each
        int ar = tid >> 2, aq = tid & 3;
        int p0a = aq * 4;
        int aks = p0a >> 3, ahalf = (p0a & 7) >> 2;
        int areg = ahalf * 2 + ((ar & 15) >> 3);
        int alb = ((ar & 7) * 4) ^ (aks << 2) ^ (ahalf << 4);
        int aoff = (((aks * 4 + (ar >> 4)) * 4 + areg) * 32) + alb;
        const float4* aptr = (const float4*)(A + (size_t)(mo + ar) * NC) + aq * 2;

        int boff[4]; const float4* bptr[4]; int brow[4];
#pragma unroll
        for (int i = 0; i < 4; i++) {
            int f = tid + i * 256;
            int n = f >> 2, p0 = (f & 3) * 4;
            int ks = p0 >> 3, reg = (p0 & 7) >> 2;
            int lb = ((n & 7) * 4) ^ (ks << 2) ^ (reg << 4);
            boff[i] = (((ks * 32 + (n >> 3)) * 2 + reg) * 32) + lb;
            bptr[i] = (const float4*)(B + (size_t)n * NC) + (f & 3) * 2;
            brow[i] = n;
        }

        float nA = 0.f, nBr[4] = {0.f, 0.f, 0.f, 0.f};
        u32 au[4], bu[4][4];

#define LDGCONV(CH)                                                          \
        do {                                                                 \
            float4 v0 = aptr[(CH) * 8], v1 = aptr[(CH) * 8 + 1];             \
            nA += v0.x*v0.x + v0.y*v0.y + v0.z*v0.z + v0.w*v0.w              \
                + v1.x*v1.x + v1.y*v1.y + v1.z*v1.z + v1.w*v1.w;             \
            au[0] = packbf(v0.x, v0.y); au[1] = packbf(v0.z, v0.w);          \
            au[2] = packbf(v1.x, v1.y); au[3] = packbf(v1.z, v1.w);          \
            _Pragma("unroll")                                                \
            for (int i_ = 0; i_ < 4; i_++) {                                 \
                float4 w0 = bptr[i_][(CH) * 8], w1 = bptr[i_][(CH) * 8 + 1]; \
                nBr[i_] += w0.x*w0.x + w0.y*w0.y + w0.z*w0.z + w0.w*w0.w     \
                         + w1.x*w1.x + w1.y*w1.y + w1.z*w1.z + w1.w*w1.w;    \
                bu[i_][0] = packbf(w0.x, w0.y); bu[i_][1] = packbf(w0.z, w0.w); \
                bu[i_][2] = packbf(w1.x, w1.y); bu[i_][3] = packbf(w1.z, w1.w); \
            }                                                                \
        } while (0)

        float acc[2][8][4];
#pragma unroll
        for (int i = 0; i < 2; i++)
#pragma unroll
            for (int j = 0; j < 8; j++)
#pragma unroll
                for (int k = 0; k < 4; k++) acc[i][j][k] = 0.f;

        LDGCONV(0);
        for (int ch = 0; ch < 16; ch++) {
            *(uint4*)&sm.c.As[aoff] = make_uint4(au[0], au[1], au[2], au[3]);
#pragma unroll
            for (int i = 0; i < 4; i++)
                *(uint4*)&sm.c.Bs[boff[i]] = make_uint4(bu[i][0], bu[i][1], bu[i][2], bu[i][3]);
            __syncthreads();
            if (ch < 15) LDGCONV(ch + 1);
#pragma unroll
            for (int ks = 0; ks < 2; ks++) {
                u32 a[2][4];
#pragma unroll
                for (int m2 = 0; m2 < 2; m2++) {
                    int mf = mw * 2 + m2;
                    int base = ((ks * 4 + mf) * 4) * 32;
#pragma unroll
                    for (int rg = 0; rg < 4; rg++)
                        a[m2][rg] = sm.c.As[base + rg * 32 + (lane ^ (ks << 2) ^ ((rg >> 1) << 4))];
                }
#pragma unroll
                for (int n2 = 0; n2 < 8; n2++) {
                    int nf = nw * 8 + n2;
                    u32 b0 = sm.c.Bs[((ks * 32 + nf) * 2 + 0) * 32 + (lane ^ (ks << 2))];
                    u32 b1 = sm.c.Bs[((ks * 32 + nf) * 2 + 1) * 32 + (lane ^ (ks << 2) ^ 16)];
                    MMA_BF16(acc[0][n2], a[0], b0, b1);
                    MMA_BF16(acc[1][n2], a[1], b0, b1);
                }
            }
            __syncthreads();
        }

        // finish norms (4-lane aligned groups)
        nA += __shfl_xor_sync(0xffffffffu, nA, 1);
        nA += __shfl_xor_sync(0xffffffffu, nA, 2);
        if (aq == 0) sm.c.rowN[ar] = nA;
#pragma unroll
        for (int i = 0; i < 4; i++) {
            float v = nBr[i];
            v += __shfl_xor_sync(0xffffffffu, v, 1);
            v += __shfl_xor_sync(0xffffffffu, v, 2);
            if ((tid & 3) == 0) sm.c.colN[brow[i]] = v;
        }
        __syncthreads();

        float naR[2][2], nbC[8][2];
#pragma unroll
        for (int m2 = 0; m2 < 2; m2++)
#pragma unroll
            for (int rh = 0; rh < 2; rh++)
                naR[m2][rh] = sm.c.rowN[(mw * 2 + m2) * 16 + (lane >> 2) + rh * 8];
#pragma unroll
        for (int n2 = 0; n2 < 8; n2++)
#pragma unroll
            for (int h = 0; h < 2; h++)
                nbC[n2][h] = sm.c.colN[nw * 64 + n2 * 8 + (lane & 3) * 2 + h];

#pragma unroll
        for (int m2 = 0; m2 < 2; m2++)
#pragma unroll
            for (int rh = 0; rh < 2; rh++) {
                ull best = ~0ULL;
#pragma unroll
                for (int n2 = 0; n2 < 8; n2++)
#pragma unroll
                    for (int h = 0; h < 2; h++) {
                        float d = fmaxf(naR[m2][rh] + nbC[n2][h] - 2.f * acc[m2][n2][rh * 2 + h], 0.f);
                        ull k = packkey(d, nw * 64 + n2 * 8 + (lane & 3) * 2 + h);
                        best = (k < best) ? k : best;
                    }
                ull o = __shfl_xor_sync(0xffffffffu, best, 1); best = (o < best) ? o : best;
                o = __shfl_xor_sync(0xffffffffu, best, 2);     best = (o < best) ? o : best;
                if ((lane & 3) == 0)
                    atomicMin(&sm.c.rowKey[(mw * 2 + m2) * 16 + (lane >> 2) + rh * 8], best);
            }

#pragma unroll
        for (int n2 = 0; n2 < 8; n2++)
#pragma unroll
            for (int h = 0; h < 2; h++) {
                ull best = ~0ULL;
#pragma unroll
                for (int m2 = 0; m2 < 2; m2++)
#pragma unroll
                    for (int rh = 0; rh < 2; rh++) {
                        float d = fmaxf(naR[m2][rh] + nbC[n2][h] - 2.f * acc[m2][n2][rh * 2 + h], 0.f);
                        ull k = packkey(d, mo + (mw * 2 + m2) * 16 + (lane >> 2) + rh * 8);
                        best = (k < best) ? k : best;
                    }
                ull o = __shfl_xor_sync(0xffffffffu, best, 4);  best = (o < best) ? o : best;
                o = __shfl_xor_sync(0xffffffffu, best, 8);      best = (o < best) ? o : best;
                o = __shfl_xor_sync(0xffffffffu, best, 16);     best = (o < best) ? o : best;
                if (lane < 4)
                    atomicMin(&sm.c.colKey[nw * 64 + n2 * 8 + (lane & 3) * 2 + h], best);
            }
        __syncthreads();
        if (tid < 64) g_key_fg[(size_t)bb * LG + mo + tid] = sm.c.rowKey[tid];
        g_colp[((size_t)bb * 9 + mt) * LL + tid] = sm.c.colKey[tid];
    } else if (blk < 320) {
        // ---------------- VICReg per-dim stats (partials) ----------------
        int idx = blk - 288;
        int j = idx * 256 + tid;
        float sa = 0, sqa = 0, sb = 0, sqb = 0, sd = 0;
#pragma unroll 8
        for (int i = 0; i < 32; i++) {
            float x = za[(size_t)i * ND + j], y = zb[(size_t)i * ND + j];
            sa += x; sqa += x * x; sb += y; sqb += y * y;
            float df = x - y; sd += df * df;
        }
        float s_a = sqa - sa * sa * (1.f / 32.f);
        float s_b = sqb - sb * sb * (1.f / 32.f);
        float va = fmaxf(0.f, 1.f - sqrtf(s_a * (1.f / 31.f) + 1e-4f));
        float vb = fmaxf(0.f, 1.f - sqrtf(s_b * (1.f / 31.f) + 1e-4f));
        float r;
        r = block_reduce(va, sm.sh);         if (tid == 0) g_statp[idx][0] = r;
        r = block_reduce(vb, sm.sh);         if (tid == 0) g_statp[idx][1] = r;
        r = block_reduce(s_a * s_a, sm.sh);  if (tid == 0) g_statp[idx][2] = r;
        r = block_reduce(s_b * s_b, sm.sh);  if (tid == 0) g_statp[idx][3] = r;
        r = block_reduce(sd, sm.sh);         if (tid == 0) g_statp[idx][4] = r;
    } else if (blk < 384) {
        // ---------------- split-K gram ----------------
        int idx = blk - 320;
        int mat = idx >> 5, chunk = idx & 31;
        int d0 = chunk * 256;
        const float* z = mat ? zb : za;
        for (int i = tid; i < 2048; i += 256) {
            int row = i >> 6, c4 = i & 63;
            float4 v = *(const float4*)(z + (size_t)row * ND + d0 + c4 * 4);
            sm.gram[row][c4 * 4 + 0] = v.x; sm.gram[row][c4 * 4 + 1] = v.y;
            sm.gram[row][c4 * 4 + 2] = v.z; sm.gram[row][c4 * 4 + 3] = v.w;
        }
        __syncthreads();
        int ia = tid >> 3, kb = (tid & 7) * 4;
        float c[4] = {};
        for (int d = 0; d < 256; d++) {
            float av = sm.gram[ia][d];
#pragma unroll
            for (int j = 0; j < 4; j++) c[j] = fmaf(av, sm.gram[kb + j][d], c[j]);
        }
#pragma unroll
        for (int j = 0; j < 4; j++) g_Rp[mat][chunk][ia * 32 + kb + j] = c[j];
    } else if (blk < 448) {
        // ---------------- grid-space NN ----------------
        int idx = blk - 384;
        int bb = idx >> 1, dir = idx & 1;
        int Lin = dir ? LL : LG, Lc = dir ? LG : LL;
        const float* gin   = dir ? gl_in : gg_in;
        const float* gcand = dir ? gg_in : gl_in;
        ull* keyout = dir ? g_key_gl : g_key_gg;
        const float2* gc = (const float2*)gcand + (size_t)bb * Lc;
        for (int i = tid; i < Lc; i += 256) sm.sc[i] = gc[i];
        __syncthreads();
        const float2* gi = (const float2*)gin + (size_t)bb * Lin;
        for (int l = tid; l < Lin; l += 256) {
            float2 g = gi[l];
            float best = 3.4e38f; int bi = 0;
            for (int m = 0; m < Lc; m++) {
                float dx = g.x - sm.sc[m].x, dy = g.y - sm.sc[m].y;
                float d = dx * dx + dy * dy;
                if (d < best) { best = d; bi = m; }
            }
            keyout[(size_t)bb * Lin + l] = packkey(best, bi);
        }
    } else {
        if (tid < 16) g_acc[tid] = 0.f;
    }
}

// ================= selection + MSE (no finale, no fences) =================
// grid (NB, 4), 576 threads. Rank by (dist, row) via unique u64 key.
__global__ void __launch_bounds__(576) selmse_kernel(const float* __restrict__ fG,
                                                     const float* __restrict__ fL) {
    int bb = blockIdx.x, which = blockIdx.y;
    int tid = threadIdx.x, lane = tid & 31, wid = tid >> 5;

    __shared__ ull sk[LG];
    __shared__ ull sk2[LG];
    __shared__ int selsh[MG];
    __shared__ int candsh[MG];
    __shared__ int warpcnt[18];
    __shared__ float shred[18];

    const float* fin; const float* fc;
    int Lin, Lc, Msel;
    if (which == 0)      { fin = fG; fc = fL; Lin = LG; Lc = LL; Msel = MG; }
    else if (which == 1) { fin = fL; fc = fG; Lin = LL; Lc = LG; Msel = ML; }
    else if (which == 2) { fin = fG; fc = fL; Lin = LG; Lc = LL; Msel = MG; }
    else                 { fin = fL; fc = fG; Lin = LL; Lc = LG; Msel = ML; }
    int accIdx = 5 + which;

    if (tid < Lin) {
        ull k;
        if (which == 0)      k = g_key_fg[(size_t)bb * LG + tid];
        else if (which == 2) k = g_key_gg[(size_t)bb * LG + tid];
        else if (which == 3) k = g_key_gl[(size_t)bb * LL + tid];
        else {
            k = ~0ULL;
#pragma unroll
            for (int s = 0; s < 9; s++) {
                ull o = g_colp[((size_t)bb * 9 + s) * LL + tid];
                k = (o < k) ? o : k;
            }
        }
        sk[tid] = k;
        sk2[tid] = (k & 0xFFFFFFFF00000000ULL) | (unsigned)tid;  // (dist, row): unique
    }
    __syncthreads();

    int myflag = 0;
    if (tid < Lin) {
        ull mine = sk2[tid];
        int cnt = 0;
#pragma unroll 8
        for (int j = 0; j < Lin; j++) cnt += (sk2[j] < mine);
        myflag = (cnt < Msel) ? 1 : 0;
    }
    u32 bal = __ballot_sync(0xffffffffu, myflag);
    if (lane == 0) warpcnt[wid] = __popc(bal);
    __syncthreads();
    if (myflag) {
        int pos = __popc(bal & ((1u << lane) - 1u));
        for (int w = 0; w < wid; w++) pos += warpcnt[w];
        selsh[pos] = tid;
        candsh[pos] = (int)(sk[tid] & 0xffffffffULL);
    }
    __syncthreads();

    const float4* fin4 = (const float4*)(fin + (size_t)bb * Lin * NC);
    const float4* fc4  = (const float4*)(fc + (size_t)bb * Lc * NC);
    float s = 0.f;
    int total = Msel * (NC / 4);
    for (int idx = tid; idx < total; idx += 576) {
        int mi = idx >> 7, t = idx & 127;
        int row = selsh[mi], cand = candsh[mi];
        float4 x = fin4[row * 128 + t], y = fc4[cand * 128 + t];
        float dx = x.x - y.x, dy = x.y - y.y, dz = x.z - y.z, dw = x.w - y.w;
        s += dx * dx + dy * dy + dz * dz + dw * dw;
    }
#pragma unroll
    for (int o = 16; o; o >>= 1) s += __shfl_down_sync(0xffffffffu, s, o);
    if (lane == 0) shred[wid] = s;
    __syncthreads();
    if (wid == 0) {
        float r = (lane < 18) ? shred[lane] : 0.f;
#pragma unroll
        for (int o = 16; o; o >>= 1) r += __shfl_down_sync(0xffffffffu, r, o);
        if (lane == 0) atomicAdd(&g_acc[accIdx], r);
    }
}

// ================= final combine (standalone, parallel) =================
__global__ void __launch_bounds__(256) final_kernel(float* __restrict__ out, int out_size) {
    __shared__ __align__(16) float sR[1024];
    __shared__ float rowsum[32];
    __shared__ float sh[8];
    __shared__ float covG[2];
    __shared__ float statv[8];
    __shared__ float qsh;
    int tid = threadIdx.x, lane = tid & 31, wid = tid >> 5;

    // stats partials: 5 stats x 32 blocks
    if (tid < 160) {
        int k = tid >> 5, l = tid & 31;
        float v = g_statp[l][k];
#pragma unroll
        for (int o = 16; o; o >>= 1) v += __shfl_down_sync(0xffffffffu, v, o);
        if (l == 0) statv[k] = v;
    }

    for (int mat = 0; mat < 2; mat++) {
        {
            float4 s4 = make_float4(0.f, 0.f, 0.f, 0.f);
#pragma unroll
            for (int c = 0; c < 32; c++) {
                float4 v = *((const float4*)&g_Rp[mat][c][0] + tid);
                s4.x += v.x; s4.y += v.y; s4.z += v.z; s4.w += v.w;
            }
            *(float4*)&sR[tid * 4] = s4;
        }
        __syncthreads();
        for (int r = wid; r < 32; r += 8) {
            float s = sR[r * 32 + lane];
#pragma unroll
            for (int o = 16; o; o >>= 1) s += __shfl_down_sync(0xffffffffu, s, o);
            if (lane == 0) rowsum[r] = s;
        }
        __syncthreads();
        if (wid == 0) {
            float s = rowsum[lane];
#pragma unroll
            for (int o = 16; o; o >>= 1) s += __shfl_down_sync(0xffffffffu, s, o);
            if (lane == 0) qsh = s * (1.f / 1024.f);
        }
        __syncthreads();
        float q = qsh;
        float part = 0.f;
        {
            float rsi = rowsum[tid >> 3] * (1.f / 32.f);
#pragma unroll
            for (int j = 0; j < 4; j++) {
                int t = tid * 4 + j;
                int k = t & 31;
                float g = sR[t] - rsi - rowsum[k] * (1.f / 32.f) + q;
                part += g * g;
            }
        }
        float tot = block_reduce(part, sh);
        if (tid == 0) covG[mat] = tot;
        __syncthreads();
    }
    if (tid == 0) {
        float inv_g = statv[4] * (1.f / (32.f * 8192.f));
        float v = 0.5f * (statv[0] + statv[1]) * (1.f / 8192.f);
        float cov = ((covG[0] - statv[2]) + (covG[1] - statv[3])) * (1.f / (31.f * 31.f * 8192.f));
        float global_loss = 25.f * inv_g + 25.f * v + 1.f * cov;
        float mfg = g_acc[5] * (1.f / (32.f * MG * NC));
        float mfl = g_acc[6] * (1.f / (32.f * ML * NC));
        float mgg = g_acc[7] * (1.f / (32.f * MG * NC));
        float mgl = g_acc[8] * (1.f / (32.f * ML * NC));
        float local_loss = 25.f * (0.5f * (mfg + mfl) + 0.5f * (mgg + mgl));
        float res = 0.25f * global_loss + 0.75f * local_loss;
        for (int i = 0; i < out_size; i++) out[i] = res;
    }
}

extern "C" void kernel_launch(void* const* d_in, const int* in_sizes, int n_in,
                              void* d_out, int out_size) {
    (void)in_sizes; (void)n_in;
    const float* zg = (const float*)d_in[0];   // (32, 8192)
    const float* zl = (const float*)d_in[1];   // (32, 8192)
    const float* fg = (const float*)d_in[2];   // (32, 576, 512)
    const float* fl = (const float*)d_in[3];   // (32, 256, 512)
    const float* gg = (const float*)d_in[4];   // (32, 576, 2)
    const float* gl = (const float*)d_in[5];   // (32, 256, 2)
    float* out = (float*)d_out;

    mega_kernel<<<449, 256>>>(zg, zl, fg, fl, gg, gl);
    {
        dim3 grid(NB, 4);
        selmse_kernel<<<grid, 576>>>(fg, fl);
    }
    final_kernel<<<1, 256>>>(out, out_size);
}